// round 9
// baseline (speedup 1.0000x reference)
#include <cuda_runtime.h>
#include <cstdint>

#define MAXN 100096
#define MAXE 1600000
#define DD 64

typedef unsigned long long ull;

// Scratch (allocation-free rule: __device__ globals)
__device__ float g_bufA[MAXN * DD];
__device__ float g_bufB[MAXN * DD];
__device__ float g_hin [MAXN * DD];
__device__ int   g_off [MAXN + 1];
__device__ int   g_cur [MAXN];
__device__ int   g_csr [MAXE];
__device__ int   g_bsum[128];

// ---------------------------------------------------------------------------
// f32x2 packed helpers (sm_100a)
// ---------------------------------------------------------------------------
__device__ __forceinline__ ull pack2(float lo, float hi) {
    ull r; asm("mov.b64 %0,{%1,%2};" : "=l"(r) : "f"(lo), "f"(hi)); return r;
}
__device__ __forceinline__ void unpack2(ull v, float& lo, float& hi) {
    asm("mov.b64 {%0,%1},%2;" : "=f"(lo), "=f"(hi) : "l"(v));
}
__device__ __forceinline__ void ffma2(ull& acc, ull a, ull b) {
    asm("fma.rn.f32x2 %0,%1,%2,%0;" : "+l"(acc) : "l"(a), "l"(b));
}
__device__ __forceinline__ ull add2(ull a, ull b) {
    ull r; asm("add.rn.f32x2 %0,%1,%2;" : "=l"(r) : "l"(a), "l"(b)); return r;
}

// ---------------------------------------------------------------------------
// CSR build: histogram -> scan -> fill   (R5-proven, unchanged)
// ---------------------------------------------------------------------------
__global__ void hist_kernel(const int* __restrict__ dst, int E,
                            int* __restrict__ deg) {
    int i = blockIdx.x * 256 + threadIdx.x;
    if (i < E) atomicAdd(&deg[__ldg(dst + i)], 1);
}

__global__ void scan1_kernel(const int* __restrict__ deg, int n,
                             int* __restrict__ off, int* __restrict__ bsum) {
    __shared__ int s[1024];
    int i = blockIdx.x * 1024 + threadIdx.x;
    int v = (i < n) ? deg[i] : 0;
    s[threadIdx.x] = v;
    __syncthreads();
    #pragma unroll
    for (int d = 1; d < 1024; d <<= 1) {
        int t = (threadIdx.x >= d) ? s[threadIdx.x - d] : 0;
        __syncthreads();
        s[threadIdx.x] += t;
        __syncthreads();
    }
    if (i < n) off[i] = s[threadIdx.x] - v;          // block-local exclusive
    if (threadIdx.x == 1023) bsum[blockIdx.x] = s[1023];
}

__global__ void scan2_kernel(int* bsum, int nb) {
    if (threadIdx.x == 0 && blockIdx.x == 0) {
        int run = 0;
        for (int b = 0; b < nb; b++) { int t = bsum[b]; bsum[b] = run; run += t; }
    }
}

__global__ void scan3_kernel(int* __restrict__ off, int* __restrict__ cur,
                             const int* __restrict__ bsum, int n, int E) {
    int i = blockIdx.x * 256 + threadIdx.x;
    if (i < n) {
        int v = off[i] + bsum[i >> 10];
        off[i] = v;
        cur[i] = v;
    }
    if (i == 0) off[n] = E;
}

__global__ void fill_kernel(const int* __restrict__ src,
                            const int* __restrict__ dst, int E,
                            int* __restrict__ cur, int* __restrict__ csr) {
    int i = blockIdx.x * 256 + threadIdx.x;
    if (i < E) {
        int d = __ldg(dst + i);
        int p = atomicAdd(&cur[d], 1);
        csr[p] = __ldg(src + i);
    }
}

// ---------------------------------------------------------------------------
// Gather: hin[i] = (1+eps)*x[i] + sum_{j in N_in(i)} x[j]   (R5, unchanged)
// ---------------------------------------------------------------------------
__global__ void __launch_bounds__(256) gather_kernel(
    const float* __restrict__ x,
    const int*   __restrict__ off,
    const int*   __restrict__ csr,
    const float* __restrict__ eps, int l,
    float*       __restrict__ out, int n)
{
    int idx = blockIdx.x * 256 + threadIdx.x;
    int node = idx >> 4;
    if (node >= n) return;
    int c = idx & 15;

    const float4* X = (const float4*)x;
    float e1 = 1.0f + __ldg(eps + l);
    float4 s0 = __ldg(X + (size_t)node * 16 + c);
    float ax = e1 * s0.x, ay = e1 * s0.y, az = e1 * s0.z, aw = e1 * s0.w;

    int beg = __ldg(off + node);
    int end = __ldg(off + node + 1);
    int j = beg;
    for (; j + 3 < end; j += 4) {
        int n0 = __ldg(csr + j);
        int n1 = __ldg(csr + j + 1);
        int n2 = __ldg(csr + j + 2);
        int n3 = __ldg(csr + j + 3);
        float4 a = __ldg(X + (size_t)n0 * 16 + c);
        float4 b = __ldg(X + (size_t)n1 * 16 + c);
        float4 d = __ldg(X + (size_t)n2 * 16 + c);
        float4 e = __ldg(X + (size_t)n3 * 16 + c);
        ax += (a.x + b.x) + (d.x + e.x);
        ay += (a.y + b.y) + (d.y + e.y);
        az += (a.z + b.z) + (d.z + e.z);
        aw += (a.w + b.w) + (d.w + e.w);
    }
    for (; j < end; j++) {
        float4 a = __ldg(X + (size_t)__ldg(csr + j) * 16 + c);
        ax += a.x; ay += a.y; az += a.z; aw += a.w;
    }
    ((float4*)out)[(size_t)node * 16 + c] = make_float4(ax, ay, az, aw);
}

// ---------------------------------------------------------------------------
// GIN MLP — quad-split (the ONE change vs R5):
//   4 lanes per row: s = tid&3; GEMM1: kh1=s&1 (k-half), ch1=s>>1 (col-half).
//   Each lane: in[32] regs, 16 packed accs over its 32 cols. Partial sums
//   reduced with shfl.xor(1) -> each lane holds full h for its col-half,
//   which IS exactly its k-half for GEMM2 (kh2=ch1, ch2=kh1). Second
//   reduction shfl.xor(2). No barriers in the loop, h never in SMEM.
//   Weights in SMEM with pad-swizzled layout:
//     WOFF(k,j) = (k>>5)*2312 + (k&31)*72 + (j>>5)*36 + (j&31)
//   -> the 4 lane-classes hit 4 distinct bank-quads (offsets 0/4/8/12 mod 32)
//   -> conflict-free 64B LDS.128 wavefronts.
//   224 thr/block, 3 blocks/SM (97-reg cap), 56 rows per block-pass.
//   SMEM: W1 2312*2 | W2 2312*2 | b1 64 | b2 64 = 9376 floats (static).
// ---------------------------------------------------------------------------
#define WKH   2312                    // floats per k-half section
#define SMW1  0
#define SMW2  4624
#define SMB1  9248
#define SMB2  9312
#define MLP_THREADS 224

__device__ __forceinline__ int woff(int k, int j) {
    return ((k >> 5) * WKH) + ((k & 31) * 72) + ((j >> 5) * 36) + (j & 31);
}

__global__ void __launch_bounds__(MLP_THREADS, 3) gin_mlp_kernel(
    const float* __restrict__ hin,
    const float* __restrict__ W1g, const float* __restrict__ b1g,
    const float* __restrict__ W2g, const float* __restrict__ b2g,
    int l, float* __restrict__ xout, int n, int nGroups)
{
    __shared__ float sm[9376];
    const int tid = threadIdx.x;

    // Stage weights into swizzled layout + biases (once per block)
    for (int idx = tid; idx < 1024; idx += MLP_THREADS) {
        int k = idx >> 4;
        int j = (idx & 15) * 4;
        float4 v1 = __ldg((const float4*)(W1g + (size_t)l * 4096) + idx);
        float4 v2 = __ldg((const float4*)(W2g + (size_t)l * 4096) + idx);
        int o = woff(k, j);
        *(float4*)(sm + SMW1 + o) = v1;
        *(float4*)(sm + SMW2 + o) = v2;
    }
    if (tid < 64)       sm[SMB1 + tid]        = __ldg(b1g + l * 64 + tid);
    else if (tid < 128) sm[SMB2 + (tid - 64)] = __ldg(b2g + l * 64 + (tid - 64));
    __syncthreads();

    const int s   = tid & 3;
    const int kh1 = s & 1;        // GEMM1 k-half
    const int ch1 = s >> 1;       // GEMM1 col-half
    const int kh2 = ch1;          // GEMM2 k-half  (owns h[ch1*32..])
    const int ch2 = kh1;          // GEMM2 col-half
    const int rowIn = tid >> 2;   // 0..55

    const float* w1 = sm + SMW1 + kh1 * WKH + ch1 * 36;
    const float* w2 = sm + SMW2 + kh2 * WKH + ch2 * 36;
    const ull*  bp1 = (const ull*)(sm + SMB1 + ch1 * 32);
    const ull*  bp2 = (const ull*)(sm + SMB2 + ch2 * 32);

    for (int grp = blockIdx.x; grp < nGroups; grp += gridDim.x) {
        const int row = grp * 56 + rowIn;
        const bool act = row < n;

        // ---- load my k-half of the input row (32 floats)
        float in[32];
        if (act) {
            const float4* p = (const float4*)(hin + (size_t)row * DD + kh1 * 32);
            #pragma unroll
            for (int u = 0; u < 8; u++) {
                float4 v = __ldg(p + u);
                in[4*u+0] = v.x; in[4*u+1] = v.y;
                in[4*u+2] = v.z; in[4*u+3] = v.w;
            }
        } else {
            #pragma unroll
            for (int u = 0; u < 32; u++) in[u] = 0.0f;
        }

        // ---- GEMM1 partial: my k-half x my col-half (32x32)
        ull acc[16];
        #pragma unroll
        for (int p = 0; p < 16; p++) acc[p] = kh1 ? 0ULL : bp1[p];

        #pragma unroll
        for (int kl = 0; kl < 32; kl++) {
            ull a2 = pack2(in[kl], in[kl]);
            const ulonglong2* w = (const ulonglong2*)(w1 + kl * 72);
            #pragma unroll
            for (int i = 0; i < 8; i++) {
                ulonglong2 ww = w[i];
                ffma2(acc[2*i],   a2, ww.x);
                ffma2(acc[2*i+1], a2, ww.y);
            }
        }

        // ---- reduce k-halves (xor 1), relu -> h (my col-half = my GEMM2 k-half)
        float h[32];
        #pragma unroll
        for (int p = 0; p < 16; p++) {
            ull other = __shfl_xor_sync(0xffffffffu, acc[p], 1);
            ull sum = add2(acc[p], other);
            float lo, hi; unpack2(sum, lo, hi);
            h[2*p]   = fmaxf(lo, 0.0f);
            h[2*p+1] = fmaxf(hi, 0.0f);
        }

        // ---- GEMM2 partial: my h k-half x my col-half (32x32)
        #pragma unroll
        for (int p = 0; p < 16; p++) acc[p] = kh2 ? 0ULL : bp2[p];

        #pragma unroll
        for (int kl = 0; kl < 32; kl++) {
            ull a2 = pack2(h[kl], h[kl]);
            const ulonglong2* w = (const ulonglong2*)(w2 + kl * 72);
            #pragma unroll
            for (int i = 0; i < 8; i++) {
                ulonglong2 ww = w[i];
                ffma2(acc[2*i],   a2, ww.x);
                ffma2(acc[2*i+1], a2, ww.y);
            }
        }

        // ---- reduce k-halves (xor 2), relu, write my 16-col quarter
        #pragma unroll
        for (int p = 0; p < 16; p++) {
            ull other = __shfl_xor_sync(0xffffffffu, acc[p], 2);
            acc[p] = add2(acc[p], other);
        }
        if (act) {
            const int q  = ((s & 1) << 1) | (s >> 1);  // output quarter 0..3
            const int pb = (s >> 1) * 8;               // local pair base
            float4* o = (float4*)(xout + (size_t)row * DD + q * 16);
            #pragma unroll
            for (int u = 0; u < 4; u++) {
                float f0, f1, f2, f3;
                unpack2(acc[pb + 2*u],     f0, f1);
                unpack2(acc[pb + 2*u + 1], f2, f3);
                o[u] = make_float4(fmaxf(f0, 0.f), fmaxf(f1, 0.f),
                                   fmaxf(f2, 0.f), fmaxf(f3, 0.f));
            }
        }
    }
}

// ---------------------------------------------------------------------------
// Final projection: out = x @ Wf + bf  (no relu), f32x2   (R5, unchanged)
// ---------------------------------------------------------------------------
__global__ void __launch_bounds__(256) final_kernel(
    const float* __restrict__ xin,
    const float* __restrict__ Wf,
    const float* __restrict__ bf,
    float* __restrict__ out, int n, int nTiles)
{
    __shared__ float Ws[4096 + 64];
    const int tid = threadIdx.x;
    {
        const float4* g = (const float4*)Wf;
        float4* s = (float4*)Ws;
        for (int i = tid; i < 1024; i += 256) s[i] = g[i];
        if (tid < 64) Ws[4096 + tid] = bf[tid];
    }
    __syncthreads();

    for (int tile = blockIdx.x; tile < nTiles; tile += gridDim.x) {
        int row = tile * 256 + tid;
        bool act = row < n;

        float in[64];
        if (act) {
            const float4* xr = (const float4*)(xin + (size_t)row * DD);
            #pragma unroll
            for (int k = 0; k < 16; k++) {
                float4 a = __ldg(xr + k);
                in[4*k+0] = a.x; in[4*k+1] = a.y; in[4*k+2] = a.z; in[4*k+3] = a.w;
            }
        } else {
            #pragma unroll
            for (int k = 0; k < 64; k++) in[k] = 0.0f;
        }

        #pragma unroll 1
        for (int jt = 0; jt < 4; jt++) {
            ull acc[8];
            const ull* bp = (const ull*)(Ws + 4096 + jt * 16);
            #pragma unroll
            for (int p = 0; p < 8; p++) acc[p] = bp[p];

            #pragma unroll
            for (int k = 0; k < 64; k++) {
                ull a2 = pack2(in[k], in[k]);
                const ulonglong2* w =
                    (const ulonglong2*)(Ws + (k << 6) + (jt << 4));
                ulonglong2 w0 = w[0], w1 = w[1], w2 = w[2], w3 = w[3];
                ffma2(acc[0], a2, w0.x); ffma2(acc[1], a2, w0.y);
                ffma2(acc[2], a2, w1.x); ffma2(acc[3], a2, w1.y);
                ffma2(acc[4], a2, w2.x); ffma2(acc[5], a2, w2.y);
                ffma2(acc[6], a2, w3.x); ffma2(acc[7], a2, w3.y);
            }
            if (act) {
                float f[16];
                #pragma unroll
                for (int p = 0; p < 8; p++) unpack2(acc[p], f[2*p], f[2*p+1]);
                float4* o = (float4*)(out + (size_t)row * DD + jt * 16);
                o[0] = make_float4(f[ 0], f[ 1], f[ 2], f[ 3]);
                o[1] = make_float4(f[ 4], f[ 5], f[ 6], f[ 7]);
                o[2] = make_float4(f[ 8], f[ 9], f[10], f[11]);
                o[3] = make_float4(f[12], f[13], f[14], f[15]);
            }
        }
    }
}

// ---------------------------------------------------------------------------
// Launch: CSR build once, then 3 x (gather; MLP) + final projection.
// All default-stream, graph-capturable, allocation-free.  (R5 structure)
// ---------------------------------------------------------------------------
extern "C" void kernel_launch(void* const* d_in, const int* in_sizes, int n_in,
                              void* d_out, int out_size)
{
    const float* x   = (const float*)d_in[0];
    const int*   ei  = (const int*)  d_in[1];
    const float* W1  = (const float*)d_in[2];
    const float* b1  = (const float*)d_in[3];
    const float* W2  = (const float*)d_in[4];
    const float* b2  = (const float*)d_in[5];
    const float* eps = (const float*)d_in[6];
    const float* Wf  = (const float*)d_in[7];
    const float* bf  = (const float*)d_in[8];

    const int n = in_sizes[0] / DD;
    const int E = in_sizes[1] / 2;
    const int* src = ei;
    const int* dst = ei + E;

    float *bufA, *bufB, *hin;
    int *off, *cur, *csr, *bsum;
    cudaGetSymbolAddress((void**)&bufA, g_bufA);
    cudaGetSymbolAddress((void**)&bufB, g_bufB);
    cudaGetSymbolAddress((void**)&hin,  g_hin);
    cudaGetSymbolAddress((void**)&off,  g_off);
    cudaGetSymbolAddress((void**)&cur,  g_cur);
    cudaGetSymbolAddress((void**)&csr,  g_csr);
    cudaGetSymbolAddress((void**)&bsum, g_bsum);

    // ---- CSR build
    cudaMemsetAsync(cur, 0, (size_t)n * sizeof(int));
    hist_kernel<<<(E + 255) / 256, 256>>>(dst, E, cur);
    const int nb = (n + 1023) / 1024;
    scan1_kernel<<<nb, 1024>>>(cur, n, off, bsum);
    scan2_kernel<<<1, 32>>>(bsum, nb);
    scan3_kernel<<<(n + 255) / 256, 256>>>(off, cur, bsum, n, E);
    fill_kernel<<<(E + 255) / 256, 256>>>(src, dst, E, cur, csr);

    // ---- Layers
    const int gatherBlocks = (n * 16 + 255) / 256;
    const int nGroups = (n + 55) / 56;       // 56 rows per block-pass
    int mlpGrid = 444;                       // 3 blocks x 148 SMs
    if (mlpGrid > nGroups) mlpGrid = nGroups;

    const float* curx = x;
    float*       nxt  = bufA;
    for (int l = 0; l < 3; l++) {
        gather_kernel<<<gatherBlocks, 256>>>(curx, off, csr, eps, l, hin, n);
        gin_mlp_kernel<<<mlpGrid, MLP_THREADS>>>(
            hin, W1, b1, W2, b2, l, nxt, n, nGroups);
        curx = nxt;
        nxt = (curx == bufA) ? bufB : bufA;
    }

    const int fTiles = (n + 255) / 256;
    int fGrid = 296;
    if (fGrid > fTiles) fGrid = fTiles;
    final_kernel<<<fGrid, 256>>>(curx, Wf, bf, (float*)d_out, n, fTiles);
}

// round 10
// speedup vs baseline: 1.3979x; 1.3979x over previous
#include <cuda_runtime.h>
#include <cuda_fp16.h>
#include <cstdint>

#define MAXN 100096
#define MAXE 1600000
#define DD 64

typedef unsigned long long ull;

// Scratch (allocation-free rule: __device__ globals)
__device__ float  g_bufA[MAXN * DD];
__device__ float  g_bufB[MAXN * DD];
__device__ float  g_hin [MAXN * DD];
__device__ __half g_xh  [MAXN * DD];    // fp16 mirror of current x
__device__ int    g_off [MAXN + 1];
__device__ int    g_cur [MAXN];
__device__ int    g_csr [MAXE];
__device__ int    g_bsum[128];

// ---------------------------------------------------------------------------
// f32x2 packed helpers (sm_100a)
// ---------------------------------------------------------------------------
__device__ __forceinline__ ull pack2(float lo, float hi) {
    ull r; asm("mov.b64 %0,{%1,%2};" : "=l"(r) : "f"(lo), "f"(hi)); return r;
}
__device__ __forceinline__ void unpack2(ull v, float& lo, float& hi) {
    asm("mov.b64 {%0,%1},%2;" : "=f"(lo), "=f"(hi) : "l"(v));
}
__device__ __forceinline__ void ffma2(ull& acc, ull a, ull b) {
    asm("fma.rn.f32x2 %0,%1,%2,%0;" : "+l"(acc) : "l"(a), "l"(b));
}
__device__ __forceinline__ uint32_t ph2(float a, float b) {
    __half2 h = __floats2half2_rn(a, b);
    return *(uint32_t*)&h;
}
__device__ __forceinline__ float4 h8_to_f4(uint2 v) {   // 4 halves -> 4 floats
    float2 a = __half22float2(*(__half2*)&v.x);
    float2 b = __half22float2(*(__half2*)&v.y);
    return make_float4(a.x, a.y, b.x, b.y);
}

// ---------------------------------------------------------------------------
// CSR build: histogram -> scan -> fill   (R5-proven, unchanged)
// ---------------------------------------------------------------------------
__global__ void hist_kernel(const int* __restrict__ dst, int E,
                            int* __restrict__ deg) {
    int i = blockIdx.x * 256 + threadIdx.x;
    if (i < E) atomicAdd(&deg[__ldg(dst + i)], 1);
}

__global__ void scan1_kernel(const int* __restrict__ deg, int n,
                             int* __restrict__ off, int* __restrict__ bsum) {
    __shared__ int s[1024];
    int i = blockIdx.x * 1024 + threadIdx.x;
    int v = (i < n) ? deg[i] : 0;
    s[threadIdx.x] = v;
    __syncthreads();
    #pragma unroll
    for (int d = 1; d < 1024; d <<= 1) {
        int t = (threadIdx.x >= d) ? s[threadIdx.x - d] : 0;
        __syncthreads();
        s[threadIdx.x] += t;
        __syncthreads();
    }
    if (i < n) off[i] = s[threadIdx.x] - v;          // block-local exclusive
    if (threadIdx.x == 1023) bsum[blockIdx.x] = s[1023];
}

__global__ void scan2_kernel(int* bsum, int nb) {
    if (threadIdx.x == 0 && blockIdx.x == 0) {
        int run = 0;
        for (int b = 0; b < nb; b++) { int t = bsum[b]; bsum[b] = run; run += t; }
    }
}

__global__ void scan3_kernel(int* __restrict__ off, int* __restrict__ cur,
                             const int* __restrict__ bsum, int n, int E) {
    int i = blockIdx.x * 256 + threadIdx.x;
    if (i < n) {
        int v = off[i] + bsum[i >> 10];
        off[i] = v;
        cur[i] = v;
    }
    if (i == 0) off[n] = E;
}

__global__ void fill_kernel(const int* __restrict__ src,
                            const int* __restrict__ dst, int E,
                            int* __restrict__ cur, int* __restrict__ csr) {
    int i = blockIdx.x * 256 + threadIdx.x;
    if (i < E) {
        int d = __ldg(dst + i);
        int p = atomicAdd(&cur[d], 1);
        csr[p] = __ldg(src + i);
    }
}

// ---------------------------------------------------------------------------
// fp32 -> fp16 mirror of the input x (once per call)
// ---------------------------------------------------------------------------
__global__ void x2h_kernel(const float* __restrict__ x,
                           __half* __restrict__ xh, int total4) {
    int i = blockIdx.x * 256 + threadIdx.x;
    if (i < total4) {
        float4 v = __ldg((const float4*)x + i);
        uint2 u;
        u.x = ph2(v.x, v.y);
        u.y = ph2(v.z, v.w);
        ((uint2*)xh)[i] = u;
    }
}

// ---------------------------------------------------------------------------
// Gather: hin[i] = (1+eps)*x[i](fp32) + sum_{j in N_in(i)} xh[j](fp16)
// 16 threads per node; neighbor rows read as fp16 (128B/row) -> half L2 bytes.
// ---------------------------------------------------------------------------
__global__ void __launch_bounds__(256) gather_kernel(
    const float*  __restrict__ x,
    const __half* __restrict__ xh,
    const int*    __restrict__ off,
    const int*    __restrict__ csr,
    const float*  __restrict__ eps, int l,
    float*        __restrict__ out, int n)
{
    int idx = blockIdx.x * 256 + threadIdx.x;
    int node = idx >> 4;
    if (node >= n) return;
    int c = idx & 15;

    const uint2* XH = (const uint2*)xh;
    float e1 = 1.0f + __ldg(eps + l);
    float4 s0 = __ldg((const float4*)x + (size_t)node * 16 + c);
    float ax = e1 * s0.x, ay = e1 * s0.y, az = e1 * s0.z, aw = e1 * s0.w;

    int beg = __ldg(off + node);
    int end = __ldg(off + node + 1);
    int j = beg;
    for (; j + 3 < end; j += 4) {
        int n0 = __ldg(csr + j);
        int n1 = __ldg(csr + j + 1);
        int n2 = __ldg(csr + j + 2);
        int n3 = __ldg(csr + j + 3);
        float4 a = h8_to_f4(__ldg(XH + (size_t)n0 * 16 + c));
        float4 b = h8_to_f4(__ldg(XH + (size_t)n1 * 16 + c));
        float4 d = h8_to_f4(__ldg(XH + (size_t)n2 * 16 + c));
        float4 e = h8_to_f4(__ldg(XH + (size_t)n3 * 16 + c));
        ax += (a.x + b.x) + (d.x + e.x);
        ay += (a.y + b.y) + (d.y + e.y);
        az += (a.z + b.z) + (d.z + e.z);
        aw += (a.w + b.w) + (d.w + e.w);
    }
    for (; j < end; j++) {
        float4 a = h8_to_f4(__ldg(XH + (size_t)__ldg(csr + j) * 16 + c));
        ax += a.x; ay += a.y; az += a.z; aw += a.w;
    }
    ((float4*)out)[(size_t)node * 16 + c] = make_float4(ax, ay, az, aw);
}

// ---------------------------------------------------------------------------
// GIN MLP (R5-proven structure): 1 row/thread, f32x2, weights in SMEM,
// h staged in per-thread SMEM column. Epilogue additionally writes the fp16
// mirror (xh) for the next layer's gather.
// SMEM floats: b1(64) b2(64) W1(4096) W2(4096) h(16384 = 64x256) = 98816 B
// ---------------------------------------------------------------------------
#define SM_B1 0
#define SM_B2 64
#define SM_W1 128
#define SM_W2 (128 + 4096)
#define SM_H  (128 + 8192)
#define MLP_SMEM_BYTES ((128 + 8192 + 16384) * 4)

__global__ void __launch_bounds__(256, 2) gin_mlp_kernel(
    const float* __restrict__ hin,
    const float* __restrict__ W1g, const float* __restrict__ b1g,
    const float* __restrict__ W2g, const float* __restrict__ b2g,
    int l, float* __restrict__ xout, __half* __restrict__ xh,
    int n, int nTiles)
{
    extern __shared__ float sm[];
    const int tid = threadIdx.x;
    {
        const float4* g1 = (const float4*)(W1g + (size_t)l * 4096);
        const float4* g2 = (const float4*)(W2g + (size_t)l * 4096);
        float4* s1 = (float4*)(sm + SM_W1);
        float4* s2 = (float4*)(sm + SM_W2);
        for (int i = tid; i < 1024; i += 256) { s1[i] = g1[i]; s2[i] = g2[i]; }
        if (tid < 64)       sm[SM_B1 + tid]        = b1g[l * 64 + tid];
        else if (tid < 128) sm[SM_B2 + (tid - 64)] = b2g[l * 64 + (tid - 64)];
    }
    __syncthreads();
    ull* hs = (ull*)sm + 0;        // placeholder; real hs below
    hs = (ull*)(sm + SM_H);        // h staging: [32 pair-rows][256 threads]

    for (int tile = blockIdx.x; tile < nTiles; tile += gridDim.x) {
        int row = tile * 256 + tid;
        bool act = row < n;

        float in[64];
        if (act) {
            const float4* xr = (const float4*)(hin + (size_t)row * DD);
            #pragma unroll
            for (int k = 0; k < 16; k++) {
                float4 a = __ldg(xr + k);
                in[4*k+0] = a.x; in[4*k+1] = a.y; in[4*k+2] = a.z; in[4*k+3] = a.w;
            }
        } else {
            #pragma unroll
            for (int k = 0; k < 64; k++) in[k] = 0.0f;
        }

        // ---- GEMM1: h = relu(in @ W1 + b1) -> SMEM column (packed pairs)
        #pragma unroll 1
        for (int jt = 0; jt < 4; jt++) {
            ull acc[8];
            const ull* bp = (const ull*)(sm + SM_B1 + jt * 16);
            #pragma unroll
            for (int p = 0; p < 8; p++) acc[p] = bp[p];

            #pragma unroll
            for (int k = 0; k < 64; k++) {
                ull a2 = pack2(in[k], in[k]);
                const ulonglong2* w =
                    (const ulonglong2*)(sm + SM_W1 + (k << 6) + (jt << 4));
                ulonglong2 w0 = w[0], w1 = w[1], w2 = w[2], w3 = w[3];
                ffma2(acc[0], a2, w0.x); ffma2(acc[1], a2, w0.y);
                ffma2(acc[2], a2, w1.x); ffma2(acc[3], a2, w1.y);
                ffma2(acc[4], a2, w2.x); ffma2(acc[5], a2, w2.y);
                ffma2(acc[6], a2, w3.x); ffma2(acc[7], a2, w3.y);
            }
            #pragma unroll
            for (int p = 0; p < 8; p++) {
                float lo, hi; unpack2(acc[p], lo, hi);
                hs[(jt * 8 + p) * 256 + tid] = pack2(fmaxf(lo, 0.f), fmaxf(hi, 0.f));
            }
        }

        // ---- GEMM2: out = relu(h @ W2 + b2)  (+ fp16 mirror write)
        #pragma unroll 1
        for (int jt = 0; jt < 4; jt++) {
            ull acc[8];
            const ull* bp = (const ull*)(sm + SM_B2 + jt * 16);
            #pragma unroll
            for (int p = 0; p < 8; p++) acc[p] = bp[p];

            #pragma unroll
            for (int k2 = 0; k2 < 32; k2++) {
                float h0, h1; unpack2(hs[k2 * 256 + tid], h0, h1);
                ull a0 = pack2(h0, h0);
                ull a1 = pack2(h1, h1);
                const ulonglong2* wA =
                    (const ulonglong2*)(sm + SM_W2 + ((2*k2)   << 6) + (jt << 4));
                const ulonglong2* wB =
                    (const ulonglong2*)(sm + SM_W2 + ((2*k2+1) << 6) + (jt << 4));
                ulonglong2 u0 = wA[0], u1 = wA[1], u2 = wA[2], u3 = wA[3];
                ffma2(acc[0], a0, u0.x); ffma2(acc[1], a0, u0.y);
                ffma2(acc[2], a0, u1.x); ffma2(acc[3], a0, u1.y);
                ffma2(acc[4], a0, u2.x); ffma2(acc[5], a0, u2.y);
                ffma2(acc[6], a0, u3.x); ffma2(acc[7], a0, u3.y);
                ulonglong2 v0 = wB[0], v1 = wB[1], v2 = wB[2], v3 = wB[3];
                ffma2(acc[0], a1, v0.x); ffma2(acc[1], a1, v0.y);
                ffma2(acc[2], a1, v1.x); ffma2(acc[3], a1, v1.y);
                ffma2(acc[4], a1, v2.x); ffma2(acc[5], a1, v2.y);
                ffma2(acc[6], a1, v3.x); ffma2(acc[7], a1, v3.y);
            }
            if (act) {
                float f[16];
                #pragma unroll
                for (int p = 0; p < 8; p++) {
                    float lo, hi; unpack2(acc[p], lo, hi);
                    f[2*p]   = fmaxf(lo, 0.f);
                    f[2*p+1] = fmaxf(hi, 0.f);
                }
                float4* o = (float4*)(xout + (size_t)row * DD + jt * 16);
                o[0] = make_float4(f[ 0], f[ 1], f[ 2], f[ 3]);
                o[1] = make_float4(f[ 4], f[ 5], f[ 6], f[ 7]);
                o[2] = make_float4(f[ 8], f[ 9], f[10], f[11]);
                o[3] = make_float4(f[12], f[13], f[14], f[15]);
                // fp16 mirror (32B per jt, aligned)
                uint4* oh = (uint4*)(xh + (size_t)row * DD + jt * 16);
                uint4 u0, u1;
                u0.x = ph2(f[ 0], f[ 1]); u0.y = ph2(f[ 2], f[ 3]);
                u0.z = ph2(f[ 4], f[ 5]); u0.w = ph2(f[ 6], f[ 7]);
                u1.x = ph2(f[ 8], f[ 9]); u1.y = ph2(f[10], f[11]);
                u1.z = ph2(f[12], f[13]); u1.w = ph2(f[14], f[15]);
                oh[0] = u0; oh[1] = u1;
            }
        }
    }
}

// ---------------------------------------------------------------------------
// Final projection: out = x @ Wf + bf  (no relu), f32x2   (R5, unchanged)
// ---------------------------------------------------------------------------
__global__ void __launch_bounds__(256) final_kernel(
    const float* __restrict__ xin,
    const float* __restrict__ Wf,
    const float* __restrict__ bf,
    float* __restrict__ out, int n, int nTiles)
{
    __shared__ float Ws[4096 + 64];
    const int tid = threadIdx.x;
    {
        const float4* g = (const float4*)Wf;
        float4* s = (float4*)Ws;
        for (int i = tid; i < 1024; i += 256) s[i] = g[i];
        if (tid < 64) Ws[4096 + tid] = bf[tid];
    }
    __syncthreads();

    for (int tile = blockIdx.x; tile < nTiles; tile += gridDim.x) {
        int row = tile * 256 + tid;
        bool act = row < n;

        float in[64];
        if (act) {
            const float4* xr = (const float4*)(xin + (size_t)row * DD);
            #pragma unroll
            for (int k = 0; k < 16; k++) {
                float4 a = __ldg(xr + k);
                in[4*k+0] = a.x; in[4*k+1] = a.y; in[4*k+2] = a.z; in[4*k+3] = a.w;
            }
        } else {
            #pragma unroll
            for (int k = 0; k < 64; k++) in[k] = 0.0f;
        }

        #pragma unroll 1
        for (int jt = 0; jt < 4; jt++) {
            ull acc[8];
            const ull* bp = (const ull*)(Ws + 4096 + jt * 16);
            #pragma unroll
            for (int p = 0; p < 8; p++) acc[p] = bp[p];

            #pragma unroll
            for (int k = 0; k < 64; k++) {
                ull a2 = pack2(in[k], in[k]);
                const ulonglong2* w =
                    (const ulonglong2*)(Ws + (k << 6) + (jt << 4));
                ulonglong2 w0 = w[0], w1 = w[1], w2 = w[2], w3 = w[3];
                ffma2(acc[0], a2, w0.x); ffma2(acc[1], a2, w0.y);
                ffma2(acc[2], a2, w1.x); ffma2(acc[3], a2, w1.y);
                ffma2(acc[4], a2, w2.x); ffma2(acc[5], a2, w2.y);
                ffma2(acc[6], a2, w3.x); ffma2(acc[7], a2, w3.y);
            }
            if (act) {
                float f[16];
                #pragma unroll
                for (int p = 0; p < 8; p++) unpack2(acc[p], f[2*p], f[2*p+1]);
                float4* o = (float4*)(out + (size_t)row * DD + jt * 16);
                o[0] = make_float4(f[ 0], f[ 1], f[ 2], f[ 3]);
                o[1] = make_float4(f[ 4], f[ 5], f[ 6], f[ 7]);
                o[2] = make_float4(f[ 8], f[ 9], f[10], f[11]);
                o[3] = make_float4(f[12], f[13], f[14], f[15]);
            }
        }
    }
}

// ---------------------------------------------------------------------------
// Launch: CSR build + x->fp16 convert, then 3 x (gather; MLP) + final.
// All default-stream, graph-capturable, allocation-free.
// ---------------------------------------------------------------------------
extern "C" void kernel_launch(void* const* d_in, const int* in_sizes, int n_in,
                              void* d_out, int out_size)
{
    const float* x   = (const float*)d_in[0];
    const int*   ei  = (const int*)  d_in[1];
    const float* W1  = (const float*)d_in[2];
    const float* b1  = (const float*)d_in[3];
    const float* W2  = (const float*)d_in[4];
    const float* b2  = (const float*)d_in[5];
    const float* eps = (const float*)d_in[6];
    const float* Wf  = (const float*)d_in[7];
    const float* bf  = (const float*)d_in[8];

    const int n = in_sizes[0] / DD;
    const int E = in_sizes[1] / 2;
    const int* src = ei;
    const int* dst = ei + E;

    float *bufA, *bufB, *hin;
    __half* xh;
    int *off, *cur, *csr, *bsum;
    cudaGetSymbolAddress((void**)&bufA, g_bufA);
    cudaGetSymbolAddress((void**)&bufB, g_bufB);
    cudaGetSymbolAddress((void**)&hin,  g_hin);
    cudaGetSymbolAddress((void**)&xh,   g_xh);
    cudaGetSymbolAddress((void**)&off,  g_off);
    cudaGetSymbolAddress((void**)&cur,  g_cur);
    cudaGetSymbolAddress((void**)&csr,  g_csr);
    cudaGetSymbolAddress((void**)&bsum, g_bsum);

    cudaFuncSetAttribute(gin_mlp_kernel,
                         cudaFuncAttributeMaxDynamicSharedMemorySize,
                         MLP_SMEM_BYTES);

    // ---- CSR build + input fp16 mirror
    cudaMemsetAsync(cur, 0, (size_t)n * sizeof(int));
    hist_kernel<<<(E + 255) / 256, 256>>>(dst, E, cur);
    x2h_kernel<<<(n * 16 + 255) / 256, 256>>>(x, xh, n * 16);
    const int nb = (n + 1023) / 1024;
    scan1_kernel<<<nb, 1024>>>(cur, n, off, bsum);
    scan2_kernel<<<1, 32>>>(bsum, nb);
    scan3_kernel<<<(n + 255) / 256, 256>>>(off, cur, bsum, n, E);
    fill_kernel<<<(E + 255) / 256, 256>>>(src, dst, E, cur, csr);

    // ---- Layers
    const int gatherBlocks = (n * 16 + 255) / 256;
    const int mlpTiles = (n + 255) / 256;
    int mlpGrid = 296;                       // 2 blocks x 148 SMs
    if (mlpGrid > mlpTiles) mlpGrid = mlpTiles;

    const float* curx = x;
    float*       nxt  = bufA;
    for (int l = 0; l < 3; l++) {
        gather_kernel<<<gatherBlocks, 256>>>(curx, xh, off, csr, eps, l, hin, n);
        gin_mlp_kernel<<<mlpGrid, 256, MLP_SMEM_BYTES>>>(
            hin, W1, b1, W2, b2, l, nxt, xh, n, mlpTiles);
        curx = nxt;
        nxt = (curx == bufA) ? bufB : bufA;
    }

    final_kernel<<<mlpGrid, 256>>>(curx, Wf, bf, (float*)d_out, n, mlpTiles);
}

// round 11
// speedup vs baseline: 1.4109x; 1.0093x over previous
#include <cuda_runtime.h>
#include <cuda_fp16.h>
#include <cstdint>

#define MAXN 100096
#define MAXE 1600000
#define DD 64

typedef unsigned long long ull;

// Scratch (allocation-free rule: __device__ globals)
__device__ float  g_bufA[MAXN * DD];
__device__ float  g_bufB[MAXN * DD];
__device__ float  g_hin [MAXN * DD];
__device__ __half g_xh  [MAXN * DD];    // fp16 mirror of current x
__device__ int    g_off [MAXN + 1];
__device__ int    g_cur [MAXN];
__device__ int    g_csr [MAXE];
__device__ int    g_bsum[128];

// ---------------------------------------------------------------------------
// f32x2 packed helpers (sm_100a)
// ---------------------------------------------------------------------------
__device__ __forceinline__ ull pack2(float lo, float hi) {
    ull r; asm("mov.b64 %0,{%1,%2};" : "=l"(r) : "f"(lo), "f"(hi)); return r;
}
__device__ __forceinline__ void unpack2(ull v, float& lo, float& hi) {
    asm("mov.b64 {%0,%1},%2;" : "=f"(lo), "=f"(hi) : "l"(v));
}
__device__ __forceinline__ void ffma2(ull& acc, ull a, ull b) {
    asm("fma.rn.f32x2 %0,%1,%2,%0;" : "+l"(acc) : "l"(a), "l"(b));
}
__device__ __forceinline__ uint32_t ph2(float a, float b) {
    __half2 h = __floats2half2_rn(a, b);
    return *(uint32_t*)&h;
}
// accumulate 8 halves (one uint4) into 8 fp32 accumulators
__device__ __forceinline__ void acc_h8(uint4 v, float* a) {
    float2 f;
    f = __half22float2(*(__half2*)&v.x); a[0] += f.x; a[1] += f.y;
    f = __half22float2(*(__half2*)&v.y); a[2] += f.x; a[3] += f.y;
    f = __half22float2(*(__half2*)&v.z); a[4] += f.x; a[5] += f.y;
    f = __half22float2(*(__half2*)&v.w); a[6] += f.x; a[7] += f.y;
}

// ---------------------------------------------------------------------------
// CSR build: histogram -> scan -> fill
// ---------------------------------------------------------------------------
__global__ void hist_kernel(const int* __restrict__ dst, int E,
                            int* __restrict__ deg) {
    int i = blockIdx.x * 256 + threadIdx.x;
    if (i < E) atomicAdd(&deg[__ldg(dst + i)], 1);
}

__global__ void scan1_kernel(const int* __restrict__ deg, int n,
                             int* __restrict__ off, int* __restrict__ bsum) {
    __shared__ int s[1024];
    int i = blockIdx.x * 1024 + threadIdx.x;
    int v = (i < n) ? deg[i] : 0;
    s[threadIdx.x] = v;
    __syncthreads();
    #pragma unroll
    for (int d = 1; d < 1024; d <<= 1) {
        int t = (threadIdx.x >= d) ? s[threadIdx.x - d] : 0;
        __syncthreads();
        s[threadIdx.x] += t;
        __syncthreads();
    }
    if (i < n) off[i] = s[threadIdx.x] - v;          // block-local exclusive
    if (threadIdx.x == 1023) bsum[blockIdx.x] = s[1023];
}

// warp-parallel exclusive scan of bsum (single warp, serial carry by chunk)
__global__ void scan2_kernel(int* bsum, int nb) {
    int lane = threadIdx.x;
    int carry = 0;
    for (int base = 0; base < nb; base += 32) {
        int i = base + lane;
        int orig = (i < nb) ? bsum[i] : 0;
        int v = orig;
        #pragma unroll
        for (int d = 1; d < 32; d <<= 1) {
            int t = __shfl_up_sync(0xffffffffu, v, d);
            if (lane >= d) v += t;
        }
        if (i < nb) bsum[i] = carry + v - orig;      // exclusive
        carry += __shfl_sync(0xffffffffu, v, 31);
    }
}

__global__ void scan3_kernel(int* __restrict__ off, int* __restrict__ cur,
                             const int* __restrict__ bsum, int n, int E) {
    int i = blockIdx.x * 256 + threadIdx.x;
    if (i < n) {
        int v = off[i] + bsum[i >> 10];
        off[i] = v;
        cur[i] = v;
    }
    if (i == 0) off[n] = E;
}

__global__ void fill_kernel(const int* __restrict__ src,
                            const int* __restrict__ dst, int E,
                            int* __restrict__ cur, int* __restrict__ csr) {
    int i = blockIdx.x * 256 + threadIdx.x;
    if (i < E) {
        int d = __ldg(dst + i);
        int p = atomicAdd(&cur[d], 1);
        csr[p] = __ldg(src + i);
    }
}

// ---------------------------------------------------------------------------
// fp32 -> fp16 mirror of the input x (once per call)
// ---------------------------------------------------------------------------
__global__ void x2h_kernel(const float* __restrict__ x,
                           __half* __restrict__ xh, int total4) {
    int i = blockIdx.x * 256 + threadIdx.x;
    if (i < total4) {
        float4 v = __ldg((const float4*)x + i);
        uint2 u;
        u.x = ph2(v.x, v.y);
        u.y = ph2(v.z, v.w);
        ((uint2*)xh)[i] = u;
    }
}

// ---------------------------------------------------------------------------
// Gather: hin[i] = (1+eps)*x[i](fp32) + sum_{j in N_in(i)} xh[j](fp16)
// 8 lanes per node, uint4 (16B) fp16 neighbor loads:
//   per edge: 8 LDG.128 (vs 16 narrow LDGs before) -> half the LDG issue.
// ---------------------------------------------------------------------------
__global__ void __launch_bounds__(256) gather_kernel(
    const float*  __restrict__ x,
    const __half* __restrict__ xh,
    const int*    __restrict__ off,
    const int*    __restrict__ csr,
    const float*  __restrict__ eps, int l,
    float*        __restrict__ out, int n)
{
    int idx = blockIdx.x * 256 + threadIdx.x;
    int node = idx >> 3;
    if (node >= n) return;
    int c = idx & 7;               // lane's 8-float slice of the 64-float row

    const uint4* XH = (const uint4*)xh;     // 8 x uint4 per row
    float e1 = 1.0f + __ldg(eps + l);

    float a[8];
    {
        const float4* X4 = (const float4*)x + (size_t)node * 16 + 2 * c;
        float4 s0 = __ldg(X4);
        float4 s1 = __ldg(X4 + 1);
        a[0] = e1 * s0.x; a[1] = e1 * s0.y; a[2] = e1 * s0.z; a[3] = e1 * s0.w;
        a[4] = e1 * s1.x; a[5] = e1 * s1.y; a[6] = e1 * s1.z; a[7] = e1 * s1.w;
    }

    int beg = __ldg(off + node);
    int end = __ldg(off + node + 1);
    int j = beg;
    for (; j + 3 < end; j += 4) {
        int n0 = __ldg(csr + j);
        int n1 = __ldg(csr + j + 1);
        int n2 = __ldg(csr + j + 2);
        int n3 = __ldg(csr + j + 3);
        uint4 v0 = __ldg(XH + (size_t)n0 * 8 + c);
        uint4 v1 = __ldg(XH + (size_t)n1 * 8 + c);
        uint4 v2 = __ldg(XH + (size_t)n2 * 8 + c);
        uint4 v3 = __ldg(XH + (size_t)n3 * 8 + c);
        acc_h8(v0, a); acc_h8(v1, a); acc_h8(v2, a); acc_h8(v3, a);
    }
    for (; j < end; j++) {
        uint4 v = __ldg(XH + (size_t)__ldg(csr + j) * 8 + c);
        acc_h8(v, a);
    }

    float4* o = (float4*)out + (size_t)node * 16 + 2 * c;
    o[0] = make_float4(a[0], a[1], a[2], a[3]);
    o[1] = make_float4(a[4], a[5], a[6], a[7]);
}

// ---------------------------------------------------------------------------
// GIN MLP (R5-proven structure): 1 row/thread, f32x2, weights in SMEM,
// h staged in per-thread SMEM column. Epilogue also writes the fp16 mirror.
// SMEM floats: b1(64) b2(64) W1(4096) W2(4096) h(16384 = 64x256) = 98816 B
// ---------------------------------------------------------------------------
#define SM_B1 0
#define SM_B2 64
#define SM_W1 128
#define SM_W2 (128 + 4096)
#define SM_H  (128 + 8192)
#define MLP_SMEM_BYTES ((128 + 8192 + 16384) * 4)

__global__ void __launch_bounds__(256, 2) gin_mlp_kernel(
    const float* __restrict__ hin,
    const float* __restrict__ W1g, const float* __restrict__ b1g,
    const float* __restrict__ W2g, const float* __restrict__ b2g,
    int l, float* __restrict__ xout, __half* __restrict__ xh,
    int n, int nTiles)
{
    extern __shared__ float sm[];
    const int tid = threadIdx.x;
    {
        const float4* g1 = (const float4*)(W1g + (size_t)l * 4096);
        const float4* g2 = (const float4*)(W2g + (size_t)l * 4096);
        float4* s1 = (float4*)(sm + SM_W1);
        float4* s2 = (float4*)(sm + SM_W2);
        for (int i = tid; i < 1024; i += 256) { s1[i] = g1[i]; s2[i] = g2[i]; }
        if (tid < 64)       sm[SM_B1 + tid]        = b1g[l * 64 + tid];
        else if (tid < 128) sm[SM_B2 + (tid - 64)] = b2g[l * 64 + (tid - 64)];
    }
    __syncthreads();
    ull* hs = (ull*)(sm + SM_H);   // h staging: [32 pair-rows][256 threads]

    for (int tile = blockIdx.x; tile < nTiles; tile += gridDim.x) {
        int row = tile * 256 + tid;
        bool act = row < n;

        float in[64];
        if (act) {
            const float4* xr = (const float4*)(hin + (size_t)row * DD);
            #pragma unroll
            for (int k = 0; k < 16; k++) {
                float4 a = __ldg(xr + k);
                in[4*k+0] = a.x; in[4*k+1] = a.y; in[4*k+2] = a.z; in[4*k+3] = a.w;
            }
        } else {
            #pragma unroll
            for (int k = 0; k < 64; k++) in[k] = 0.0f;
        }

        // ---- GEMM1: h = relu(in @ W1 + b1) -> SMEM column (packed pairs)
        #pragma unroll 1
        for (int jt = 0; jt < 4; jt++) {
            ull acc[8];
            const ull* bp = (const ull*)(sm + SM_B1 + jt * 16);
            #pragma unroll
            for (int p = 0; p < 8; p++) acc[p] = bp[p];

            #pragma unroll
            for (int k = 0; k < 64; k++) {
                ull a2 = pack2(in[k], in[k]);
                const ulonglong2* w =
                    (const ulonglong2*)(sm + SM_W1 + (k << 6) + (jt << 4));
                ulonglong2 w0 = w[0], w1 = w[1], w2 = w[2], w3 = w[3];
                ffma2(acc[0], a2, w0.x); ffma2(acc[1], a2, w0.y);
                ffma2(acc[2], a2, w1.x); ffma2(acc[3], a2, w1.y);
                ffma2(acc[4], a2, w2.x); ffma2(acc[5], a2, w2.y);
                ffma2(acc[6], a2, w3.x); ffma2(acc[7], a2, w3.y);
            }
            #pragma unroll
            for (int p = 0; p < 8; p++) {
                float lo, hi; unpack2(acc[p], lo, hi);
                hs[(jt * 8 + p) * 256 + tid] = pack2(fmaxf(lo, 0.f), fmaxf(hi, 0.f));
            }
        }

        // ---- GEMM2: out = relu(h @ W2 + b2)  (+ fp16 mirror write)
        #pragma unroll 1
        for (int jt = 0; jt < 4; jt++) {
            ull acc[8];
            const ull* bp = (const ull*)(sm + SM_B2 + jt * 16);
            #pragma unroll
            for (int p = 0; p < 8; p++) acc[p] = bp[p];

            #pragma unroll
            for (int k2 = 0; k2 < 32; k2++) {
                float h0, h1; unpack2(hs[k2 * 256 + tid], h0, h1);
                ull a0 = pack2(h0, h0);
                ull a1 = pack2(h1, h1);
                const ulonglong2* wA =
                    (const ulonglong2*)(sm + SM_W2 + ((2*k2)   << 6) + (jt << 4));
                const ulonglong2* wB =
                    (const ulonglong2*)(sm + SM_W2 + ((2*k2+1) << 6) + (jt << 4));
                ulonglong2 u0 = wA[0], u1 = wA[1], u2 = wA[2], u3 = wA[3];
                ffma2(acc[0], a0, u0.x); ffma2(acc[1], a0, u0.y);
                ffma2(acc[2], a0, u1.x); ffma2(acc[3], a0, u1.y);
                ffma2(acc[4], a0, u2.x); ffma2(acc[5], a0, u2.y);
                ffma2(acc[6], a0, u3.x); ffma2(acc[7], a0, u3.y);
                ulonglong2 v0 = wB[0], v1 = wB[1], v2 = wB[2], v3 = wB[3];
                ffma2(acc[0], a1, v0.x); ffma2(acc[1], a1, v0.y);
                ffma2(acc[2], a1, v1.x); ffma2(acc[3], a1, v1.y);
                ffma2(acc[4], a1, v2.x); ffma2(acc[5], a1, v2.y);
                ffma2(acc[6], a1, v3.x); ffma2(acc[7], a1, v3.y);
            }
            if (act) {
                float f[16];
                #pragma unroll
                for (int p = 0; p < 8; p++) {
                    float lo, hi; unpack2(acc[p], lo, hi);
                    f[2*p]   = fmaxf(lo, 0.f);
                    f[2*p+1] = fmaxf(hi, 0.f);
                }
                float4* o = (float4*)(xout + (size_t)row * DD + jt * 16);
                o[0] = make_float4(f[ 0], f[ 1], f[ 2], f[ 3]);
                o[1] = make_float4(f[ 4], f[ 5], f[ 6], f[ 7]);
                o[2] = make_float4(f[ 8], f[ 9], f[10], f[11]);
                o[3] = make_float4(f[12], f[13], f[14], f[15]);
                // fp16 mirror (32B per jt, aligned)
                uint4* oh = (uint4*)(xh + (size_t)row * DD + jt * 16);
                uint4 u0h, u1h;
                u0h.x = ph2(f[ 0], f[ 1]); u0h.y = ph2(f[ 2], f[ 3]);
                u0h.z = ph2(f[ 4], f[ 5]); u0h.w = ph2(f[ 6], f[ 7]);
                u1h.x = ph2(f[ 8], f[ 9]); u1h.y = ph2(f[10], f[11]);
                u1h.z = ph2(f[12], f[13]); u1h.w = ph2(f[14], f[15]);
                oh[0] = u0h; oh[1] = u1h;
            }
        }
    }
}

// ---------------------------------------------------------------------------
// Final projection: out = x @ Wf + bf  (no relu), f32x2
// ---------------------------------------------------------------------------
__global__ void __launch_bounds__(256) final_kernel(
    const float* __restrict__ xin,
    const float* __restrict__ Wf,
    const float* __restrict__ bf,
    float* __restrict__ out, int n, int nTiles)
{
    __shared__ float Ws[4096 + 64];
    const int tid = threadIdx.x;
    {
        const float4* g = (const float4*)Wf;
        float4* s = (float4*)Ws;
        for (int i = tid; i < 1024; i += 256) s[i] = g[i];
        if (tid < 64) Ws[4096 + tid] = bf[tid];
    }
    __syncthreads();

    for (int tile = blockIdx.x; tile < nTiles; tile += gridDim.x) {
        int row = tile * 256 + tid;
        bool act = row < n;

        float in[64];
        if (act) {
            const float4* xr = (const float4*)(xin + (size_t)row * DD);
            #pragma unroll
            for (int k = 0; k < 16; k++) {
                float4 a = __ldg(xr + k);
                in[4*k+0] = a.x; in[4*k+1] = a.y; in[4*k+2] = a.z; in[4*k+3] = a.w;
            }
        } else {
            #pragma unroll
            for (int k = 0; k < 64; k++) in[k] = 0.0f;
        }

        #pragma unroll 1
        for (int jt = 0; jt < 4; jt++) {
            ull acc[8];
            const ull* bp = (const ull*)(Ws + 4096 + jt * 16);
            #pragma unroll
            for (int p = 0; p < 8; p++) acc[p] = bp[p];

            #pragma unroll
            for (int k = 0; k < 64; k++) {
                ull a2 = pack2(in[k], in[k]);
                const ulonglong2* w =
                    (const ulonglong2*)(Ws + (k << 6) + (jt << 4));
                ulonglong2 w0 = w[0], w1 = w[1], w2 = w[2], w3 = w[3];
                ffma2(acc[0], a2, w0.x); ffma2(acc[1], a2, w0.y);
                ffma2(acc[2], a2, w1.x); ffma2(acc[3], a2, w1.y);
                ffma2(acc[4], a2, w2.x); ffma2(acc[5], a2, w2.y);
                ffma2(acc[6], a2, w3.x); ffma2(acc[7], a2, w3.y);
            }
            if (act) {
                float f[16];
                #pragma unroll
                for (int p = 0; p < 8; p++) unpack2(acc[p], f[2*p], f[2*p+1]);
                float4* o = (float4*)(out + (size_t)row * DD + jt * 16);
                o[0] = make_float4(f[ 0], f[ 1], f[ 2], f[ 3]);
                o[1] = make_float4(f[ 4], f[ 5], f[ 6], f[ 7]);
                o[2] = make_float4(f[ 8], f[ 9], f[10], f[11]);
                o[3] = make_float4(f[12], f[13], f[14], f[15]);
            }
        }
    }
}

// ---------------------------------------------------------------------------
// Launch: CSR build + x->fp16 convert, then 3 x (gather; MLP) + final.
// All default-stream, graph-capturable, allocation-free.
// ---------------------------------------------------------------------------
extern "C" void kernel_launch(void* const* d_in, const int* in_sizes, int n_in,
                              void* d_out, int out_size)
{
    const float* x   = (const float*)d_in[0];
    const int*   ei  = (const int*)  d_in[1];
    const float* W1  = (const float*)d_in[2];
    const float* b1  = (const float*)d_in[3];
    const float* W2  = (const float*)d_in[4];
    const float* b2  = (const float*)d_in[5];
    const float* eps = (const float*)d_in[6];
    const float* Wf  = (const float*)d_in[7];
    const float* bf  = (const float*)d_in[8];

    const int n = in_sizes[0] / DD;
    const int E = in_sizes[1] / 2;
    const int* src = ei;
    const int* dst = ei + E;

    float *bufA, *bufB, *hin;
    __half* xh;
    int *off, *cur, *csr, *bsum;
    cudaGetSymbolAddress((void**)&bufA, g_bufA);
    cudaGetSymbolAddress((void**)&bufB, g_bufB);
    cudaGetSymbolAddress((void**)&hin,  g_hin);
    cudaGetSymbolAddress((void**)&xh,   g_xh);
    cudaGetSymbolAddress((void**)&off,  g_off);
    cudaGetSymbolAddress((void**)&cur,  g_cur);
    cudaGetSymbolAddress((void**)&csr,  g_csr);
    cudaGetSymbolAddress((void**)&bsum, g_bsum);

    cudaFuncSetAttribute(gin_mlp_kernel,
                         cudaFuncAttributeMaxDynamicSharedMemorySize,
                         MLP_SMEM_BYTES);

    // ---- CSR build + input fp16 mirror
    cudaMemsetAsync(cur, 0, (size_t)n * sizeof(int));
    hist_kernel<<<(E + 255) / 256, 256>>>(dst, E, cur);
    x2h_kernel<<<(n * 16 + 255) / 256, 256>>>(x, xh, n * 16);
    const int nb = (n + 1023) / 1024;
    scan1_kernel<<<nb, 1024>>>(cur, n, off, bsum);
    scan2_kernel<<<1, 32>>>(bsum, nb);
    scan3_kernel<<<(n + 255) / 256, 256>>>(off, cur, bsum, n, E);
    fill_kernel<<<(E + 255) / 256, 256>>>(src, dst, E, cur, csr);

    // ---- Layers
    const int gatherBlocks = (n * 8 + 255) / 256;
    const int mlpTiles = (n + 255) / 256;
    int mlpGrid = 296;                       // 2 blocks x 148 SMs
    if (mlpGrid > mlpTiles) mlpGrid = mlpTiles;

    const float* curx = x;
    float*       nxt  = bufA;
    for (int l = 0; l < 3; l++) {
        gather_kernel<<<gatherBlocks, 256>>>(curx, xh, off, csr, eps, l, hin, n);
        gin_mlp_kernel<<<mlpGrid, 256, MLP_SMEM_BYTES>>>(
            hin, W1, b1, W2, b2, l, nxt, xh, n, mlpTiles);
        curx = nxt;
        nxt = (curx == bufA) ? bufB : bufA;
    }

    final_kernel<<<mlpGrid, 256>>>(curx, Wf, bf, (float*)d_out, n, mlpTiles);
}

// round 12
// speedup vs baseline: 2.1055x; 1.4923x over previous
#include <cuda_runtime.h>
#include <cuda_fp16.h>
#include <cstdint>

#define MAXN 100096
#define MAXE 1600000
#define DD 64

typedef unsigned long long ull;

// Scratch (allocation-free rule: __device__ globals)
__device__ float  g_bufA[MAXN * DD];
__device__ float  g_bufB[MAXN * DD];
__device__ float  g_hin [MAXN * DD];
__device__ __half g_xh  [MAXN * DD];    // fp16 mirror of current x
__device__ int    g_off [MAXN + 1];
__device__ int    g_cur [MAXN];
__device__ int    g_csr [MAXE];
__device__ int    g_bsum[128];

// ---------------------------------------------------------------------------
// packed helpers
// ---------------------------------------------------------------------------
__device__ __forceinline__ ull pack2(float lo, float hi) {
    ull r; asm("mov.b64 %0,{%1,%2};" : "=l"(r) : "f"(lo), "f"(hi)); return r;
}
__device__ __forceinline__ void unpack2(ull v, float& lo, float& hi) {
    asm("mov.b64 {%0,%1},%2;" : "=f"(lo), "=f"(hi) : "l"(v));
}
__device__ __forceinline__ void ffma2(ull& acc, ull a, ull b) {
    asm("fma.rn.f32x2 %0,%1,%2,%0;" : "+l"(acc) : "l"(a), "l"(b));
}
__device__ __forceinline__ uint32_t ph2(float a, float b) {
    __half2 h = __floats2half2_rn(a, b);
    return *(uint32_t*)&h;
}
// accumulate 8 halves (one uint4) into 8 fp32 accumulators
__device__ __forceinline__ void acc_h8(uint4 v, float* a) {
    float2 f;
    f = __half22float2(*(__half2*)&v.x); a[0] += f.x; a[1] += f.y;
    f = __half22float2(*(__half2*)&v.y); a[2] += f.x; a[3] += f.y;
    f = __half22float2(*(__half2*)&v.z); a[4] += f.x; a[5] += f.y;
    f = __half22float2(*(__half2*)&v.w); a[6] += f.x; a[7] += f.y;
}
// fp32 -> (hi fp16, lo fp16) error-compensated split
__device__ __forceinline__ void split_hl(float v, __half& h, __half& l) {
    h = __float2half_rn(v);
    l = __float2half_rn(v - __half2float(h));
}
__device__ __forceinline__ uint32_t packh(__half a, __half b) {
    __half2 t = __halves2half2(a, b);
    return *(uint32_t*)&t;
}
// m16n8k16 row.col f16 x f16 -> f32 accumulate
__device__ __forceinline__ void mma16816(
    float& c0, float& c1, float& c2, float& c3,
    uint32_t a0, uint32_t a1, uint32_t a2, uint32_t a3,
    uint32_t b0, uint32_t b1)
{
    asm volatile(
        "mma.sync.aligned.m16n8k16.row.col.f32.f16.f16.f32 "
        "{%0,%1,%2,%3},{%4,%5,%6,%7},{%8,%9},{%0,%1,%2,%3};"
        : "+f"(c0), "+f"(c1), "+f"(c2), "+f"(c3)
        : "r"(a0), "r"(a1), "r"(a2), "r"(a3), "r"(b0), "r"(b1));
}

// ---------------------------------------------------------------------------
// CSR build: histogram -> scan -> fill
// ---------------------------------------------------------------------------
__global__ void hist_kernel(const int* __restrict__ dst, int E,
                            int* __restrict__ deg) {
    int i = blockIdx.x * 256 + threadIdx.x;
    if (i < E) atomicAdd(&deg[__ldg(dst + i)], 1);
}

__global__ void scan1_kernel(const int* __restrict__ deg, int n,
                             int* __restrict__ off, int* __restrict__ bsum) {
    __shared__ int s[1024];
    int i = blockIdx.x * 1024 + threadIdx.x;
    int v = (i < n) ? deg[i] : 0;
    s[threadIdx.x] = v;
    __syncthreads();
    #pragma unroll
    for (int d = 1; d < 1024; d <<= 1) {
        int t = (threadIdx.x >= d) ? s[threadIdx.x - d] : 0;
        __syncthreads();
        s[threadIdx.x] += t;
        __syncthreads();
    }
    if (i < n) off[i] = s[threadIdx.x] - v;
    if (threadIdx.x == 1023) bsum[blockIdx.x] = s[1023];
}

__global__ void scan2_kernel(int* bsum, int nb) {
    int lane = threadIdx.x;
    int carry = 0;
    for (int base = 0; base < nb; base += 32) {
        int i = base + lane;
        int orig = (i < nb) ? bsum[i] : 0;
        int v = orig;
        #pragma unroll
        for (int d = 1; d < 32; d <<= 1) {
            int t = __shfl_up_sync(0xffffffffu, v, d);
            if (lane >= d) v += t;
        }
        if (i < nb) bsum[i] = carry + v - orig;
        carry += __shfl_sync(0xffffffffu, v, 31);
    }
}

__global__ void scan3_kernel(int* __restrict__ off, int* __restrict__ cur,
                             const int* __restrict__ bsum, int n, int E) {
    int i = blockIdx.x * 256 + threadIdx.x;
    if (i < n) {
        int v = off[i] + bsum[i >> 10];
        off[i] = v;
        cur[i] = v;
    }
    if (i == 0) off[n] = E;
}

__global__ void fill_kernel(const int* __restrict__ src,
                            const int* __restrict__ dst, int E,
                            int* __restrict__ cur, int* __restrict__ csr) {
    int i = blockIdx.x * 256 + threadIdx.x;
    if (i < E) {
        int d = __ldg(dst + i);
        int p = atomicAdd(&cur[d], 1);
        csr[p] = __ldg(src + i);
    }
}

// ---------------------------------------------------------------------------
// fp32 -> fp16 mirror of the input x (once per call)
// ---------------------------------------------------------------------------
__global__ void x2h_kernel(const float* __restrict__ x,
                           __half* __restrict__ xh, int total4) {
    int i = blockIdx.x * 256 + threadIdx.x;
    if (i < total4) {
        float4 v = __ldg((const float4*)x + i);
        uint2 u;
        u.x = ph2(v.x, v.y);
        u.y = ph2(v.z, v.w);
        ((uint2*)xh)[i] = u;
    }
}

// ---------------------------------------------------------------------------
// Gather: hin[i] = (1+eps)*x[i](fp32) + sum_{j in N_in(i)} xh[j](fp16)
// 8 lanes per node, uint4 fp16 neighbor loads.  (R11, unchanged)
// ---------------------------------------------------------------------------
__global__ void __launch_bounds__(256) gather_kernel(
    const float*  __restrict__ x,
    const __half* __restrict__ xh,
    const int*    __restrict__ off,
    const int*    __restrict__ csr,
    const float*  __restrict__ eps, int l,
    float*        __restrict__ out, int n)
{
    int idx = blockIdx.x * 256 + threadIdx.x;
    int node = idx >> 3;
    if (node >= n) return;
    int c = idx & 7;

    const uint4* XH = (const uint4*)xh;
    float e1 = 1.0f + __ldg(eps + l);

    float a[8];
    {
        const float4* X4 = (const float4*)x + (size_t)node * 16 + 2 * c;
        float4 s0 = __ldg(X4);
        float4 s1 = __ldg(X4 + 1);
        a[0] = e1 * s0.x; a[1] = e1 * s0.y; a[2] = e1 * s0.z; a[3] = e1 * s0.w;
        a[4] = e1 * s1.x; a[5] = e1 * s1.y; a[6] = e1 * s1.z; a[7] = e1 * s1.w;
    }

    int beg = __ldg(off + node);
    int end = __ldg(off + node + 1);
    int j = beg;
    for (; j + 3 < end; j += 4) {
        int n0 = __ldg(csr + j);
        int n1 = __ldg(csr + j + 1);
        int n2 = __ldg(csr + j + 2);
        int n3 = __ldg(csr + j + 3);
        uint4 v0 = __ldg(XH + (size_t)n0 * 8 + c);
        uint4 v1 = __ldg(XH + (size_t)n1 * 8 + c);
        uint4 v2 = __ldg(XH + (size_t)n2 * 8 + c);
        uint4 v3 = __ldg(XH + (size_t)n3 * 8 + c);
        acc_h8(v0, a); acc_h8(v1, a); acc_h8(v2, a); acc_h8(v3, a);
    }
    for (; j < end; j++) {
        uint4 v = __ldg(XH + (size_t)__ldg(csr + j) * 8 + c);
        acc_h8(v, a);
    }

    float4* o = (float4*)out + (size_t)node * 16 + 2 * c;
    o[0] = make_float4(a[0], a[1], a[2], a[3]);
    o[1] = make_float4(a[4], a[5], a[6], a[7]);
}

// ---------------------------------------------------------------------------
// Tensor-core GIN MLP.  8 warps/block, warp = 16 rows.  Per layer:
//   h = relu(hin @ W1 + b1); out = relu(h @ W2 + b2)
// A and W split fp16 hi+lo; 3 MMAs per k-step (err ~2^-22).
// h stays in registers: GEMM1 D-fragments repack directly into GEMM2
// A-fragments (identical thread layouts).  No block barriers in tile loop.
// SMEM (halves): W1hi/W1lo/W2hi/W2lo 4x4608 | Ahi/Alo 8 warps x 1152 each
//              + 128 floats bias  = 74240 B.
// ---------------------------------------------------------------------------
#define AST   72                       // padded halves per row
#define W1HI  0
#define W1LO  4608
#define W2HI  9216
#define W2LO  13824
#define A_HI  18432
#define A_LO  27648
#define H_TOT 36864
#define MLP_SMEM_BYTES (H_TOT * 2 + 128 * 4)

__global__ void __launch_bounds__(256, 2) gin_mlp_kernel(
    const float* __restrict__ hin,
    const float* __restrict__ W1g, const float* __restrict__ b1g,
    const float* __restrict__ W2g, const float* __restrict__ b2g,
    int l, float* __restrict__ xout, __half* __restrict__ xh,
    int n, int nTiles)
{
    extern __shared__ __half smh[];
    float* fb = (float*)(smh + H_TOT);       // b1[64], b2[64]
    const int tid  = threadIdx.x;
    const int warp = tid >> 5;
    const int lane = tid & 31;
    const int g    = lane >> 2;
    const int t    = lane & 3;

    // ---- stage weights (transposed, hi/lo split) + biases, once per block
    for (int e = tid; e < 4096; e += 256) {
        int k = e >> 6, nn = e & 63;
        float w1 = __ldg(W1g + (size_t)l * 4096 + e);
        float w2 = __ldg(W2g + (size_t)l * 4096 + e);
        __half h, lo;
        split_hl(w1, h, lo);
        smh[W1HI + nn * AST + k] = h;  smh[W1LO + nn * AST + k] = lo;
        split_hl(w2, h, lo);
        smh[W2HI + nn * AST + k] = h;  smh[W2LO + nn * AST + k] = lo;
    }
    if (tid < 64)       fb[tid]      = __ldg(b1g + l * 64 + tid);
    else if (tid < 128) fb[tid]      = __ldg(b2g + l * 64 + (tid - 64));
    __syncthreads();

    __half* Ah = smh + A_HI + warp * (16 * AST);
    __half* Al = smh + A_LO + warp * (16 * AST);

    for (int tile = blockIdx.x; tile < nTiles; tile += gridDim.x) {
        const int rowBase = tile * 128 + warp * 16;

        // ---- stage this warp's 16 rows (fp32 -> hi/lo fp16), warp-local
        __syncwarp();                       // prior tile's frag reads done
        {
            const float4* gsrc = (const float4*)hin + (size_t)rowBase * 16;
            #pragma unroll
            for (int i = 0; i < 8; i++) {
                int idx = i * 32 + lane;            // 0..255
                float4 v = __ldg(gsrc + idx);
                int r = idx >> 4, c4 = idx & 15;
                __half h0,l0,h1,l1,h2v,l2,h3,l3;
                split_hl(v.x, h0, l0); split_hl(v.y, h1, l1);
                split_hl(v.z, h2v, l2); split_hl(v.w, h3, l3);
                uint2 hh; hh.x = packh(h0, h1); hh.y = packh(h2v, h3);
                uint2 ll; ll.x = packh(l0, l1); ll.y = packh(l2, l3);
                *(uint2*)(Ah + r * AST + c4 * 4) = hh;
                *(uint2*)(Al + r * AST + c4 * 4) = ll;
            }
        }
        __syncwarp();

        // ---- load A fragments (hi + lo), 4 k-chunks
        uint32_t ah0[4], ah1[4], ah2[4], ah3[4];
        uint32_t al0[4], al1[4], al2[4], al3[4];
        #pragma unroll
        for (int kc = 0; kc < 4; kc++) {
            int o0 = g * AST + kc * 16 + 2 * t;
            int o1 = (g + 8) * AST + kc * 16 + 2 * t;
            ah0[kc] = *(const uint32_t*)(Ah + o0);
            ah1[kc] = *(const uint32_t*)(Ah + o1);
            ah2[kc] = *(const uint32_t*)(Ah + o0 + 8);
            ah3[kc] = *(const uint32_t*)(Ah + o1 + 8);
            al0[kc] = *(const uint32_t*)(Al + o0);
            al1[kc] = *(const uint32_t*)(Al + o1);
            al2[kc] = *(const uint32_t*)(Al + o0 + 8);
            al3[kc] = *(const uint32_t*)(Al + o1 + 8);
        }

        // ---- GEMM1: h fragments (8 n-chunks x 4 floats), kept in regs
        float hc[8][4];
        #pragma unroll
        for (int nc = 0; nc < 8; nc++) {
            float b0 = fb[nc * 8 + 2 * t], b1v = fb[nc * 8 + 2 * t + 1];
            float c0 = b0, c1 = b1v, c2 = b0, c3 = b1v;
            #pragma unroll
            for (int kc = 0; kc < 4; kc++) {
                const __half* ph = smh + W1HI + (nc * 8 + g) * AST + kc * 16 + 2 * t;
                const __half* pl = smh + W1LO + (nc * 8 + g) * AST + kc * 16 + 2 * t;
                uint32_t bh0 = *(const uint32_t*)ph;
                uint32_t bh1 = *(const uint32_t*)(ph + 8);
                uint32_t bl0 = *(const uint32_t*)pl;
                uint32_t bl1 = *(const uint32_t*)(pl + 8);
                mma16816(c0,c1,c2,c3, ah0[kc],ah1[kc],ah2[kc],ah3[kc], bh0,bh1);
                mma16816(c0,c1,c2,c3, al0[kc],al1[kc],al2[kc],al3[kc], bh0,bh1);
                mma16816(c0,c1,c2,c3, ah0[kc],ah1[kc],ah2[kc],ah3[kc], bl0,bl1);
            }
            hc[nc][0] = c0; hc[nc][1] = c1; hc[nc][2] = c2; hc[nc][3] = c3;
        }

        // ---- relu(h) -> GEMM2 A fragments (register repack, hi/lo)
        uint32_t bh0a[4], bh1a[4], bh2a[4], bh3a[4];
        uint32_t bl0a[4], bl1a[4], bl2a[4], bl3a[4];
        #pragma unroll
        for (int kc = 0; kc < 4; kc++) {
            float r00 = fmaxf(hc[2*kc][0], 0.f), r01 = fmaxf(hc[2*kc][1], 0.f);
            float r02 = fmaxf(hc[2*kc][2], 0.f), r03 = fmaxf(hc[2*kc][3], 0.f);
            float r10 = fmaxf(hc[2*kc+1][0], 0.f), r11 = fmaxf(hc[2*kc+1][1], 0.f);
            float r12 = fmaxf(hc[2*kc+1][2], 0.f), r13 = fmaxf(hc[2*kc+1][3], 0.f);
            __half h0,l0,h1,l1;
            split_hl(r00,h0,l0); split_hl(r01,h1,l1);
            bh0a[kc] = packh(h0,h1); bl0a[kc] = packh(l0,l1);
            split_hl(r02,h0,l0); split_hl(r03,h1,l1);
            bh1a[kc] = packh(h0,h1); bl1a[kc] = packh(l0,l1);
            split_hl(r10,h0,l0); split_hl(r11,h1,l1);
            bh2a[kc] = packh(h0,h1); bl2a[kc] = packh(l0,l1);
            split_hl(r12,h0,l0); split_hl(r13,h1,l1);
            bh3a[kc] = packh(h0,h1); bl3a[kc] = packh(l0,l1);
        }

        // ---- GEMM2 + epilogue (fp32 out + fp16 mirror)
        #pragma unroll
        for (int nc = 0; nc < 8; nc++) {
            float b0 = fb[64 + nc * 8 + 2 * t], b1v = fb[64 + nc * 8 + 2 * t + 1];
            float c0 = b0, c1 = b1v, c2 = b0, c3 = b1v;
            #pragma unroll
            for (int kc = 0; kc < 4; kc++) {
                const __half* ph = smh + W2HI + (nc * 8 + g) * AST + kc * 16 + 2 * t;
                const __half* pl = smh + W2LO + (nc * 8 + g) * AST + kc * 16 + 2 * t;
                uint32_t wh0 = *(const uint32_t*)ph;
                uint32_t wh1 = *(const uint32_t*)(ph + 8);
                uint32_t wl0 = *(const uint32_t*)pl;
                uint32_t wl1 = *(const uint32_t*)(pl + 8);
                mma16816(c0,c1,c2,c3, bh0a[kc],bh1a[kc],bh2a[kc],bh3a[kc], wh0,wh1);
                mma16816(c0,c1,c2,c3, bl0a[kc],bl1a[kc],bl2a[kc],bl3a[kc], wh0,wh1);
                mma16816(c0,c1,c2,c3, bh0a[kc],bh1a[kc],bh2a[kc],bh3a[kc], wl0,wl1);
            }
            float f0 = fmaxf(c0, 0.f), f1 = fmaxf(c1, 0.f);
            float f2 = fmaxf(c2, 0.f), f3 = fmaxf(c3, 0.f);
            int col  = nc * 8 + 2 * t;
            int row0 = rowBase + g;
            int row1 = row0 + 8;
            if (row0 < n) {
                *(float2*)(xout + (size_t)row0 * DD + col) = make_float2(f0, f1);
                *(uint32_t*)(xh + (size_t)row0 * DD + col) = ph2(f0, f1);
            }
            if (row1 < n) {
                *(float2*)(xout + (size_t)row1 * DD + col) = make_float2(f2, f3);
                *(uint32_t*)(xh + (size_t)row1 * DD + col) = ph2(f2, f3);
            }
        }
    }
}

// ---------------------------------------------------------------------------
// Final projection: out = x @ Wf + bf  (no relu), f32x2   (unchanged)
// ---------------------------------------------------------------------------
__global__ void __launch_bounds__(256) final_kernel(
    const float* __restrict__ xin,
    const float* __restrict__ Wf,
    const float* __restrict__ bf,
    float* __restrict__ out, int n, int nTiles)
{
    __shared__ float Ws[4096 + 64];
    const int tid = threadIdx.x;
    {
        const float4* g = (const float4*)Wf;
        float4* s = (float4*)Ws;
        for (int i = tid; i < 1024; i += 256) s[i] = g[i];
        if (tid < 64) Ws[4096 + tid] = bf[tid];
    }
    __syncthreads();

    for (int tile = blockIdx.x; tile < nTiles; tile += gridDim.x) {
        int row = tile * 256 + tid;
        bool act = row < n;

        float in[64];
        if (act) {
            const float4* xr = (const float4*)(xin + (size_t)row * DD);
            #pragma unroll
            for (int k = 0; k < 16; k++) {
                float4 a = __ldg(xr + k);
                in[4*k+0] = a.x; in[4*k+1] = a.y; in[4*k+2] = a.z; in[4*k+3] = a.w;
            }
        } else {
            #pragma unroll
            for (int k = 0; k < 64; k++) in[k] = 0.0f;
        }

        #pragma unroll 1
        for (int jt = 0; jt < 4; jt++) {
            ull acc[8];
            const ull* bp = (const ull*)(Ws + 4096 + jt * 16);
            #pragma unroll
            for (int p = 0; p < 8; p++) acc[p] = bp[p];

            #pragma unroll
            for (int k = 0; k < 64; k++) {
                ull a2 = pack2(in[k], in[k]);
                const ulonglong2* w =
                    (const ulonglong2*)(Ws + (k << 6) + (jt << 4));
                ulonglong2 w0 = w[0], w1 = w[1], w2 = w[2], w3 = w[3];
                ffma2(acc[0], a2, w0.x); ffma2(acc[1], a2, w0.y);
                ffma2(acc[2], a2, w1.x); ffma2(acc[3], a2, w1.y);
                ffma2(acc[4], a2, w2.x); ffma2(acc[5], a2, w2.y);
                ffma2(acc[6], a2, w3.x); ffma2(acc[7], a2, w3.y);
            }
            if (act) {
                float f[16];
                #pragma unroll
                for (int p = 0; p < 8; p++) unpack2(acc[p], f[2*p], f[2*p+1]);
                float4* o = (float4*)(out + (size_t)row * DD + jt * 16);
                o[0] = make_float4(f[ 0], f[ 1], f[ 2], f[ 3]);
                o[1] = make_float4(f[ 4], f[ 5], f[ 6], f[ 7]);
                o[2] = make_float4(f[ 8], f[ 9], f[10], f[11]);
                o[3] = make_float4(f[12], f[13], f[14], f[15]);
            }
        }
    }
}

// ---------------------------------------------------------------------------
// Launch
// ---------------------------------------------------------------------------
extern "C" void kernel_launch(void* const* d_in, const int* in_sizes, int n_in,
                              void* d_out, int out_size)
{
    const float* x   = (const float*)d_in[0];
    const int*   ei  = (const int*)  d_in[1];
    const float* W1  = (const float*)d_in[2];
    const float* b1  = (const float*)d_in[3];
    const float* W2  = (const float*)d_in[4];
    const float* b2  = (const float*)d_in[5];
    const float* eps = (const float*)d_in[6];
    const float* Wf  = (const float*)d_in[7];
    const float* bf  = (const float*)d_in[8];

    const int n = in_sizes[0] / DD;
    const int E = in_sizes[1] / 2;
    const int* src = ei;
    const int* dst = ei + E;

    float *bufA, *bufB, *hin;
    __half* xh;
    int *off, *cur, *csr, *bsum;
    cudaGetSymbolAddress((void**)&bufA, g_bufA);
    cudaGetSymbolAddress((void**)&bufB, g_bufB);
    cudaGetSymbolAddress((void**)&hin,  g_hin);
    cudaGetSymbolAddress((void**)&xh,   g_xh);
    cudaGetSymbolAddress((void**)&off,  g_off);
    cudaGetSymbolAddress((void**)&cur,  g_cur);
    cudaGetSymbolAddress((void**)&csr,  g_csr);
    cudaGetSymbolAddress((void**)&bsum, g_bsum);

    cudaFuncSetAttribute(gin_mlp_kernel,
                         cudaFuncAttributeMaxDynamicSharedMemorySize,
                         MLP_SMEM_BYTES);

    // ---- CSR build + input fp16 mirror
    cudaMemsetAsync(cur, 0, (size_t)n * sizeof(int));
    hist_kernel<<<(E + 255) / 256, 256>>>(dst, E, cur);
    x2h_kernel<<<(n * 16 + 255) / 256, 256>>>(x, xh, n * 16);
    const int nb = (n + 1023) / 1024;
    scan1_kernel<<<nb, 1024>>>(cur, n, off, bsum);
    scan2_kernel<<<1, 32>>>(bsum, nb);
    scan3_kernel<<<(n + 255) / 256, 256>>>(off, cur, bsum, n, E);
    fill_kernel<<<(E + 255) / 256, 256>>>(src, dst, E, cur, csr);

    // ---- Layers
    const int gatherBlocks = (n * 8 + 255) / 256;
    const int mlpTiles = (n + 127) / 128;
    int mlpGrid = 296;                        // 2 blocks x 148 SMs
    if (mlpGrid > mlpTiles) mlpGrid = mlpTiles;

    const float* curx = x;
    float*       nxt  = bufA;
    for (int l = 0; l < 3; l++) {
        gather_kernel<<<gatherBlocks, 256>>>(curx, xh, off, csr, eps, l, hin, n);
        gin_mlp_kernel<<<mlpGrid, 256, MLP_SMEM_BYTES>>>(
            hin, W1, b1, W2, b2, l, nxt, xh, n, mlpTiles);
        curx = nxt;
        nxt = (curx == bufA) ? bufB : bufA;
    }

    const int fTiles = (n + 255) / 256;
    int fGrid = 296;
    if (fGrid > fTiles) fGrid = fTiles;
    final_kernel<<<fGrid, 256>>>(curx, Wf, bf, (float*)d_out, n, fTiles);
}